// round 2
// baseline (speedup 1.0000x reference)
#include <cuda_runtime.h>
#include <cuda_bf16.h>

typedef unsigned long long ull;

#define F128 128
#define NRBF 20
#define ATS 132              // A^T shared stride (128 + 4 pad, float4-aligned, 4-way max conflict)
#define MAX_ATOMS 50000

__device__ float g_h[(size_t)MAX_ATOMS * F128];
__device__ float g_agg[(size_t)MAX_ATOMS * F128];

// ---------- f32x2 helpers ----------
__device__ __forceinline__ ull pk2(float x) {
    ull r; asm("mov.b64 %0, {%1, %1};" : "=l"(r) : "f"(x)); return r;
}
__device__ __forceinline__ ull fma2(ull a, ull b, ull c) {
    ull d; asm("fma.rn.f32x2 %0, %1, %2, %3;" : "=l"(d) : "l"(a), "l"(b), "l"(c)); return d;
}
__device__ __forceinline__ float2 upk(ull a) {
    float2 f; asm("mov.b64 {%0, %1}, %2;" : "=f"(f.x), "=f"(f.y) : "l"(a)); return f;
}
__device__ __forceinline__ void red4(float* p, float4 v) {
    asm volatile("red.global.add.v4.f32 [%0], {%1,%2,%3,%4};"
                 :: "l"(p), "f"(v.x), "f"(v.y), "f"(v.z), "f"(v.w) : "memory");
}
__device__ __forceinline__ float sspf(float x) {
    // softplus(x) - log(2), numerically stable
    float e = __expf(-fabsf(x));
    return fmaxf(x, 0.0f) + __logf(1.0f + e) - 0.69314718056f;
}

// ---------- 8x8 register-tiled GEMM core ----------
// out[m][n] (+)= sum_k sAT[k*ATS + m] * sB[k*128 + n], f32x2-packed along n
__device__ __forceinline__ void init_acc_bias(const float* sbias, int n0, ull acc[8][4]) {
    const ulonglong2* bb = (const ulonglong2*)(sbias + n0);
    ulonglong2 b0 = bb[0], b1 = bb[1];
#pragma unroll
    for (int e = 0; e < 8; e++) {
        acc[e][0] = b0.x; acc[e][1] = b0.y; acc[e][2] = b1.x; acc[e][3] = b1.y;
    }
}

__device__ __forceinline__ void gemm_core(const float* __restrict__ sAT,
                                          const float* __restrict__ sB,
                                          int m0, int n0, ull acc[8][4]) {
#pragma unroll 4
    for (int k = 0; k < 128; k++) {
        const ulonglong2* wr = (const ulonglong2*)(sB + k * 128 + n0);
        ulonglong2 wA = wr[0], wB = wr[1];
        const float4* hr = (const float4*)(sAT + k * ATS + m0);
        float4 ha = hr[0], hb = hr[1];
        ull h[8];
        h[0] = pk2(ha.x); h[1] = pk2(ha.y); h[2] = pk2(ha.z); h[3] = pk2(ha.w);
        h[4] = pk2(hb.x); h[5] = pk2(hb.y); h[6] = pk2(hb.z); h[7] = pk2(hb.w);
#pragma unroll
        for (int e = 0; e < 8; e++) {
            acc[e][0] = fma2(h[e], wA.x, acc[e][0]);
            acc[e][1] = fma2(h[e], wA.y, acc[e][1]);
            acc[e][2] = fma2(h[e], wB.x, acc[e][2]);
            acc[e][3] = fma2(h[e], wB.y, acc[e][3]);
        }
    }
}

// ---------- kernel 0: zero the aggregation buffer ----------
__global__ void k_zero(int n4) {
    int i = blockIdx.x * blockDim.x + threadIdx.x;
    if (i < n4) ((float4*)g_agg)[i] = make_float4(0.f, 0.f, 0.f, 0.f);
}

// ---------- kernel 1: h = x @ W_in + b_in ----------
// smem: sW 16384 | sb 128 | sAT 128*132
__global__ void __launch_bounds__(256) k_in(const float* __restrict__ x,
                                            const float* __restrict__ W,
                                            const float* __restrict__ b, int nRows) {
    extern __shared__ float sm[];
    float* sW = sm;
    float* sb = sW + 16384;
    float* sAT = sb + 128;
    int t = threadIdx.x;
    for (int i = t; i < 4096; i += 256) ((float4*)sW)[i] = ((const float4*)W)[i];
    if (t < 128) sb[t] = b[t];
    int tx = t & 15, ty = t >> 4;
    int nTiles = (nRows + 127) >> 7;
    for (int tile = blockIdx.x; tile < nTiles; tile += gridDim.x) {
        int r0 = tile << 7;
        __syncthreads();
        // load x tile transposed: sAT[k][row] = x[r0+row][k]
        for (int i = t; i < 4096; i += 256) {
            int row = i >> 5, kq = i & 31;
            float4 v = (r0 + row < nRows)
                           ? ((const float4*)(x + (size_t)(r0 + row) * 128))[kq]
                           : make_float4(0.f, 0.f, 0.f, 0.f);
            int kk = kq * 4;
            sAT[(kk + 0) * ATS + row] = v.x;
            sAT[(kk + 1) * ATS + row] = v.y;
            sAT[(kk + 2) * ATS + row] = v.z;
            sAT[(kk + 3) * ATS + row] = v.w;
        }
        __syncthreads();
        ull acc[8][4];
        init_acc_bias(sb, tx * 8, acc);
        gemm_core(sAT, sW, ty * 8, tx * 8, acc);
#pragma unroll
        for (int e = 0; e < 8; e++) {
            int row = r0 + ty * 8 + e;
            if (row < nRows) {
                float2 p0 = upk(acc[e][0]), p1 = upk(acc[e][1]);
                float2 p2 = upk(acc[e][2]), p3 = upk(acc[e][3]);
                float4* dst = (float4*)(g_h + (size_t)row * 128 + tx * 8);
                dst[0] = make_float4(p0.x, p0.y, p1.x, p1.y);
                dst[1] = make_float4(p2.x, p2.y, p3.x, p3.y);
            }
        }
    }
}

// ---------- kernel 2: fused edge pipeline ----------
// Wij = ssp(f_ij@Wf1+bf1)@Wf2+bf2 ; scaled by rcut; x_ij = h[idx_j]*Wij; scatter into agg[idx_i]
// smem: sWf2 16384 | sWf1 2560 | sbf1 128 | sbf2 128 | sHid 128*132 | sF 2560 | sRc 128 | sII 128 | sJJ 128
__global__ void __launch_bounds__(256) k_edge(const float* __restrict__ f_ij,
                                              const float* __restrict__ rcut,
                                              const int* __restrict__ idx_i,
                                              const int* __restrict__ idx_j,
                                              const float* __restrict__ Wf1,
                                              const float* __restrict__ bf1,
                                              const float* __restrict__ Wf2,
                                              const float* __restrict__ bf2, int nPairs) {
    extern __shared__ float sm[];
    float* sWf2 = sm;
    float* sWf1 = sWf2 + 16384;
    float* sbf1 = sWf1 + 2560;
    float* sbf2 = sbf1 + 128;
    float* sHid = sbf2 + 128;            // 128*ATS
    float* sF = sHid + 128 * ATS;        // [128 edges][20]
    float* sRc = sF + 2560;
    int* sII = (int*)(sRc + 128);
    int* sJJ = sII + 128;

    int t = threadIdx.x;
    for (int i = t; i < 4096; i += 256) ((float4*)sWf2)[i] = ((const float4*)Wf2)[i];
    for (int i = t; i < 640; i += 256) ((float4*)sWf1)[i] = ((const float4*)Wf1)[i];
    if (t < 128) { sbf1[t] = bf1[t]; sbf2[t] = bf2[t]; }
    __syncthreads();

    // phase-1 identity: thread owns hidden unit kx, half the edges
    int kx = t & 127, eh = t >> 7;
    float w1c[NRBF];
#pragma unroll
    for (int r = 0; r < NRBF; r++) w1c[r] = sWf1[r * 128 + kx];
    float b1 = sbf1[kx];
    int tx = t & 15, ty = t >> 4;

    int nTiles = nPairs >> 7;
    for (int tile = blockIdx.x; tile < nTiles; tile += gridDim.x) {
        int e0g = tile << 7;
        __syncthreads();
        for (int i = t; i < 640; i += 256)
            ((float4*)sF)[i] = ((const float4*)(f_ij + (size_t)e0g * NRBF))[i];
        if (t < 128) {
            sRc[t] = rcut[e0g + t];
            sII[t] = idx_i[e0g + t];
            sJJ[t] = idx_j[e0g + t];
        }
        __syncthreads();
        // phase 1: hidden[e][kx] = ssp(bf1 + f[e]·Wf1[:,kx]) -> sHid[kx][e]
        {
            int ebase = eh * 64;
            for (int e4 = 0; e4 < 64; e4 += 4) {
                float hv[4];
#pragma unroll
                for (int c = 0; c < 4; c++) {
                    const float4* fp = (const float4*)(sF + (ebase + e4 + c) * NRBF);
                    float a = b1;
#pragma unroll
                    for (int q = 0; q < 5; q++) {
                        float4 fv = fp[q];
                        a = fmaf(w1c[4 * q + 0], fv.x, a);
                        a = fmaf(w1c[4 * q + 1], fv.y, a);
                        a = fmaf(w1c[4 * q + 2], fv.z, a);
                        a = fmaf(w1c[4 * q + 3], fv.w, a);
                    }
                    hv[c] = sspf(a);
                }
                *(float4*)(sHid + kx * ATS + ebase + e4) =
                    make_float4(hv[0], hv[1], hv[2], hv[3]);
            }
        }
        __syncthreads();
        // phase 2: Wij[e][f] = bf2 + sum_k hid[e][k]*Wf2[k][f]
        ull acc[8][4];
        init_acc_bias(sbf2, tx * 8, acc);
        gemm_core(sHid, sWf2, ty * 8, tx * 8, acc);
        // epilogue: scale by rcut, gather h[idx_j], scatter-add agg[idx_i]
#pragma unroll
        for (int e = 0; e < 8; e++) {
            int el = ty * 8 + e;
            float rc = sRc[el];
            int jj = sJJ[el], ii = sII[el];
            float2 p0 = upk(acc[e][0]), p1 = upk(acc[e][1]);
            float2 p2 = upk(acc[e][2]), p3 = upk(acc[e][3]);
            const float4* hj = (const float4*)(g_h + (size_t)jj * 128 + tx * 8);
            float4 h0 = hj[0], h1 = hj[1];
            float4 v0 = make_float4(p0.x * rc * h0.x, p0.y * rc * h0.y,
                                    p1.x * rc * h0.z, p1.y * rc * h0.w);
            float4 v1 = make_float4(p2.x * rc * h1.x, p2.y * rc * h1.y,
                                    p3.x * rc * h1.z, p3.y * rc * h1.w);
            float* ap = g_agg + (size_t)ii * 128 + tx * 8;
            red4(ap, v0);
            red4(ap + 4, v1);
        }
    }
}

// ---------- kernel 3: out = ssp(agg@Wo1+bo1)@Wo2+bo2 ----------
// smem: sW1 16384 | sW2 16384 | sb1 128 | sb2 128 | sBuf 128*132
__global__ void __launch_bounds__(256) k_out(const float* __restrict__ Wo1,
                                             const float* __restrict__ bo1,
                                             const float* __restrict__ Wo2,
                                             const float* __restrict__ bo2,
                                             float* __restrict__ out, int nRows) {
    extern __shared__ float sm[];
    float* sW1 = sm;
    float* sW2 = sW1 + 16384;
    float* sb1 = sW2 + 16384;
    float* sb2 = sb1 + 128;
    float* sBuf = sb2 + 128;  // 128*ATS
    int t = threadIdx.x;
    for (int i = t; i < 4096; i += 256) ((float4*)sW1)[i] = ((const float4*)Wo1)[i];
    for (int i = t; i < 4096; i += 256) ((float4*)sW2)[i] = ((const float4*)Wo2)[i];
    if (t < 128) { sb1[t] = bo1[t]; sb2[t] = bo2[t]; }
    int tx = t & 15, ty = t >> 4;
    int nTiles = (nRows + 127) >> 7;
    for (int tile = blockIdx.x; tile < nTiles; tile += gridDim.x) {
        int r0 = tile << 7;
        __syncthreads();
        // load agg tile transposed
        for (int i = t; i < 4096; i += 256) {
            int row = i >> 5, kq = i & 31;
            float4 v = (r0 + row < nRows)
                           ? ((const float4*)(g_agg + (size_t)(r0 + row) * 128))[kq]
                           : make_float4(0.f, 0.f, 0.f, 0.f);
            int kk = kq * 4;
            sBuf[(kk + 0) * ATS + row] = v.x;
            sBuf[(kk + 1) * ATS + row] = v.y;
            sBuf[(kk + 2) * ATS + row] = v.z;
            sBuf[(kk + 3) * ATS + row] = v.w;
        }
        __syncthreads();
        ull acc[8][4];
        init_acc_bias(sb1, tx * 8, acc);
        gemm_core(sBuf, sW1, ty * 8, tx * 8, acc);
        __syncthreads();  // all reads of sBuf done before overwrite
        // ssp + transposed store: sBuf[f][row] = ssp(tmp[row][f])
#pragma unroll
        for (int e = 0; e < 8; e++) {
            int row = ty * 8 + e;
            float2 p0 = upk(acc[e][0]), p1 = upk(acc[e][1]);
            float2 p2 = upk(acc[e][2]), p3 = upk(acc[e][3]);
            float vals[8] = {sspf(p0.x), sspf(p0.y), sspf(p1.x), sspf(p1.y),
                             sspf(p2.x), sspf(p2.y), sspf(p3.x), sspf(p3.y)};
            int f0 = tx * 8;
#pragma unroll
            for (int c = 0; c < 8; c++) sBuf[(f0 + c) * ATS + row] = vals[c];
        }
        __syncthreads();
        ull acc2[8][4];
        init_acc_bias(sb2, tx * 8, acc2);
        gemm_core(sBuf, sW2, ty * 8, tx * 8, acc2);
#pragma unroll
        for (int e = 0; e < 8; e++) {
            int row = r0 + ty * 8 + e;
            if (row < nRows) {
                float2 p0 = upk(acc2[e][0]), p1 = upk(acc2[e][1]);
                float2 p2 = upk(acc2[e][2]), p3 = upk(acc2[e][3]);
                float4* dst = (float4*)(out + (size_t)row * 128 + tx * 8);
                dst[0] = make_float4(p0.x, p0.y, p1.x, p1.y);
                dst[1] = make_float4(p2.x, p2.y, p3.x, p3.y);
            }
        }
    }
}

// ---------- launch ----------
extern "C" void kernel_launch(void* const* d_in, const int* in_sizes, int n_in,
                              void* d_out, int out_size) {
    const float* x    = (const float*)d_in[0];
    const float* f_ij = (const float*)d_in[1];
    const float* rcut = (const float*)d_in[2];
    const float* W_in = (const float*)d_in[3];
    const float* b_in = (const float*)d_in[4];
    const float* Wf1  = (const float*)d_in[5];
    const float* bf1  = (const float*)d_in[6];
    const float* Wf2  = (const float*)d_in[7];
    const float* bf2  = (const float*)d_in[8];
    const float* Wo1  = (const float*)d_in[9];
    const float* bo1  = (const float*)d_in[10];
    const float* Wo2  = (const float*)d_in[11];
    const float* bo2  = (const float*)d_in[12];
    const int* idx_i  = (const int*)d_in[13];
    const int* idx_j  = (const int*)d_in[14];
    float* out = (float*)d_out;

    int nAtoms = in_sizes[0] / 128;
    int nPairs = in_sizes[2];

    const int SMEM_IN   = (16384 + 128 + 128 * ATS) * 4;
    const int SMEM_EDGE = (16384 + 2560 + 128 + 128 + 128 * ATS + 2560 + 128 + 128 + 128) * 4;
    const int SMEM_OUT  = (16384 + 16384 + 128 + 128 + 128 * ATS) * 4;

    cudaFuncSetAttribute(k_in, cudaFuncAttributeMaxDynamicSharedMemorySize, SMEM_IN);
    cudaFuncSetAttribute(k_edge, cudaFuncAttributeMaxDynamicSharedMemorySize, SMEM_EDGE);
    cudaFuncSetAttribute(k_out, cudaFuncAttributeMaxDynamicSharedMemorySize, SMEM_OUT);

    int n4 = nAtoms * 32;  // float4 count of agg
    k_zero<<<(n4 + 255) / 256, 256>>>(n4);

    int rowTiles = (nAtoms + 127) / 128;
    k_in<<<rowTiles, 256, SMEM_IN>>>(x, W_in, b_in, nAtoms);
    k_edge<<<304, 256, SMEM_EDGE>>>(f_ij, rcut, idx_i, idx_j, Wf1, bf1, Wf2, bf2, nPairs);
    k_out<<<rowTiles, 256, SMEM_OUT>>>(Wo1, bo1, Wo2, bo2, out, nAtoms);
}